// round 13
// baseline (speedup 1.0000x reference)
#include <cuda_runtime.h>
#include <cuda_fp16.h>
#include <cstdint>
#include <cstddef>

#define TOKENS 8192
#define KDIM   4096
#define NDIM   4096
#define NGROUPS 32

// fp16 scratch in device globals (allocation-free rule)
__device__ uint4 g_Xh4[(size_t)TOKENS * KDIM / 8];  // x as half
__device__ uint4 g_Wh4[(size_t)NDIM   * KDIM / 8];  // W as half, scale pre-applied

// ---------------------------------------------------------------------------
// Fused converter (proven: ~34 us combined, near HBM roofline)
// ---------------------------------------------------------------------------
#define CVT_THREADS 512
#define XBLK ((int)(TOKENS * (size_t)KDIM / 16 / CVT_THREADS))   // 4096 blocks
#define WBLK ((int)(NDIM   * (size_t)KDIM / 8  / CVT_THREADS))   // 4096 blocks

__global__ void __launch_bounds__(CVT_THREADS)
fused_convert_kernel(const float* __restrict__ x,
                     const int* __restrict__ wp,
                     const float* __restrict__ sc) {
    int b = blockIdx.x;
    if (b < XBLK) {
        size_t idx = ((size_t)b * CVT_THREADS + threadIdx.x) * 2;
        const float4* xv = (const float4*)x;
#pragma unroll
        for (int r = 0; r < 2; ++r) {
            float4 v0 = xv[2 * (idx + r)];
            float4 v1 = xv[2 * (idx + r) + 1];
            __half2 h0 = __floats2half2_rn(v0.x, v0.y);
            __half2 h1 = __floats2half2_rn(v0.z, v0.w);
            __half2 h2 = __floats2half2_rn(v1.x, v1.y);
            __half2 h3 = __floats2half2_rn(v1.z, v1.w);
            uint4 o;
            o.x = *reinterpret_cast<unsigned*>(&h0);
            o.y = *reinterpret_cast<unsigned*>(&h1);
            o.z = *reinterpret_cast<unsigned*>(&h2);
            o.w = *reinterpret_cast<unsigned*>(&h3);
            g_Xh4[idx + r] = o;
        }
    } else {
        size_t idx = (size_t)(b - XBLK) * CVT_THREADS + threadIdx.x;
        int4 p = ((const int4*)wp)[idx];
        int n = (int)(idx >> 9);
        int k = (int)((idx << 3) & (KDIM - 1));
        float s = __ldg(&sc[(size_t)n * NGROUPS + (k >> 7)]);
        __align__(16) __half h[8];
        h[0] = __float2half_rn((float)((p.x & 15) - 8) * s);
        h[1] = __float2half_rn((float)(((p.x >> 4) & 15) - 8) * s);
        h[2] = __float2half_rn((float)((p.y & 15) - 8) * s);
        h[3] = __float2half_rn((float)(((p.y >> 4) & 15) - 8) * s);
        h[4] = __float2half_rn((float)((p.z & 15) - 8) * s);
        h[5] = __float2half_rn((float)(((p.z >> 4) & 15) - 8) * s);
        h[6] = __float2half_rn((float)((p.w & 15) - 8) * s);
        h[7] = __float2half_rn((float)(((p.w >> 4) & 15) - 8) * s);
        g_Wh4[idx] = *reinterpret_cast<uint4*>(h);
    }
}

// ---------------------------------------------------------------------------
// GEMM: CTA 128x256, BK=128 (8 k16 slabs/stage), 2-slot mbarrier pipeline,
// 512 threads (16 warps, 2x8), warp tile 64x32, ldmatrix.
// produce(s+2) placed after the stage's last LDSM + empty-arrive (NSTAGE=2
// slot-reuse safety), covered by slab 7's 16 MMAs.
// ---------------------------------------------------------------------------
#define BM 128
#define BN 256
#define BK 128
#define NSTAGE 2
#define SAS 136                          // 128 + 8 pad halves (272B row, 17*16B)
#define A_SMEM_BYTES (BM * SAS * 2)      // 34816
#define B_SMEM_BYTES (BN * SAS * 2)      // 69632
#define STAGE_BYTES (A_SMEM_BYTES + B_SMEM_BYTES)   // 104448
#define SMEM_TOTAL (1024 + NSTAGE * STAGE_BYTES)    // 209920

#define CP16(dst, src) asm volatile("cp.async.cg.shared.global [%0], [%1], 16;" :: "r"(dst), "l"(src))
#define LDSM_X4(r0, r1, r2, r3, addr) \
    asm volatile("ldmatrix.sync.aligned.m8n8.x4.shared.b16 {%0,%1,%2,%3}, [%4];" \
        : "=r"(r0), "=r"(r1), "=r"(r2), "=r"(r3) : "r"(addr))

#define MBARRIER_INIT(addr, cnt) \
    asm volatile("mbarrier.init.shared.b64 [%0], %1;" :: "r"(addr), "r"(cnt) : "memory")
#define MBARRIER_ARRIVE(addr) \
    asm volatile("mbarrier.arrive.release.cta.shared.b64 _, [%0];" :: "r"(addr) : "memory")
#define CPASYNC_MBAR_ARRIVE_NOINC(addr) \
    asm volatile("cp.async.mbarrier.arrive.noinc.shared.b64 [%0];" :: "r"(addr) : "memory")

#define MBARRIER_WAIT(mbar, par) do { \
    uint32_t _m = (mbar), _p = (par), _d; \
    asm volatile("{\n\t.reg .pred p;\n\tmbarrier.try_wait.parity.shared.b64 p, [%1], %2;\n\tselp.b32 %0, 1, 0, p;\n\t}" \
        : "=r"(_d) : "r"(_m), "r"(_p) : "memory"); \
    if (!_d) { \
        asm volatile("{\n\t.reg .pred P1;\n\tWL_%=:\n\tmbarrier.try_wait.parity.shared.b64 P1, [%0], %1;\n\t@P1 bra.uni WD_%=;\n\tbra.uni WL_%=;\n\tWD_%=:\n\t}" \
            :: "r"(_m), "r"(_p) : "memory"); \
    } \
} while (0)

__device__ __forceinline__ uint32_t smem_u32(const void* p) {
    uint32_t a;
    asm("{ .reg .u64 t; cvta.to.shared.u64 t, %1; cvt.u32.u64 %0, t; }" : "=r"(a) : "l"(p));
    return a;
}

__global__ void __launch_bounds__(512, 1)
gemm_hmma_kernel(float* __restrict__ out) {
    extern __shared__ __align__(128) char smem[];
    const uint32_t sb = smem_u32(smem);
    const uint32_t mb_full  = sb;        // 2 x 8B
    const uint32_t mb_empty = sb + 16;   // 2 x 8B
    const uint32_t stage0   = sb + 1024;

    const int tid  = threadIdx.x;
    const int warp = tid >> 5;
    const int lane = tid & 31;
    const int wm = warp >> 3;      // 0..1 -> 64 rows
    const int wn = warp & 7;       // 0..7 -> 32 cols
    const int g  = lane >> 2;
    const int tg = lane & 3;

    const int bm = blockIdx.y * BM;
    const int bn = blockIdx.x * BN;

    const __half* __restrict__ Xh = (const __half*)g_Xh4;
    const __half* __restrict__ Wh = (const __half*)g_Wh4;

    if (tid == 0) {
#pragma unroll
        for (int s = 0; s < NSTAGE; s++) {
            MBARRIER_INIT(mb_full  + 8 * s, 512);
            MBARRIER_INIT(mb_empty + 8 * s, 512);
        }
    }
    __syncthreads();

    uint32_t aoff[4];
#pragma unroll
    for (int mt = 0; mt < 4; ++mt)
        aoff[mt] = ((wm * 64 + mt * 16 + (lane & 15)) * SAS + ((lane >> 4) << 3)) * 2;
    uint32_t boff[2];
#pragma unroll
    for (int p = 0; p < 2; ++p)
        boff[p] = A_SMEM_BYTES +
                  ((wn * 32 + p * 16 + (lane & 7) + (((lane >> 4) & 1) << 3)) * SAS +
                   (((lane >> 3) & 1) << 3)) * 2;

    float acc[4][4][4];
#pragma unroll
    for (int i = 0; i < 4; i++)
#pragma unroll
        for (int j = 0; j < 4; j++)
#pragma unroll
            for (int r = 0; r < 4; r++) acc[i][j][r] = 0.f;

    int pslot = 0, pphase = 1;   // fresh-barrier parity trick: first wait passes
    int cslot = 0, cphase = 0;

    auto produce = [&](int kt) {
        MBARRIER_WAIT(mb_empty + 8 * pslot, pphase);
        const uint32_t sbase = stage0 + pslot * STAGE_BYTES;
        const int k0 = kt * BK;
        // A: 128 rows x 128 halves = 2048 chunks of 16B
#pragma unroll
        for (int i = 0; i < 4; ++i) {
            int c = tid + i * 512;
            int row = c >> 4, col = (c & 15) << 3;
            CP16(sbase + (row * SAS + col) * 2,
                 Xh + (size_t)(bm + row) * KDIM + k0 + col);
        }
        // B: 256 rows x 128 halves = 4096 chunks
#pragma unroll
        for (int i = 0; i < 8; ++i) {
            int c = tid + i * 512;
            int row = c >> 4, col = (c & 15) << 3;
            CP16(sbase + A_SMEM_BYTES + (row * SAS + col) * 2,
                 Wh + (size_t)(bn + row) * KDIM + k0 + col);
        }
        CPASYNC_MBAR_ARRIVE_NOINC(mb_full + 8 * pslot);
        if (++pslot == NSTAGE) { pslot = 0; pphase ^= 1; }
    };

    auto mma_row = [&](int mt, const uint32_t a[4], const uint32_t b[4][2]) {
#pragma unroll
        for (int nt = 0; nt < 4; ++nt) {
            asm volatile(
                "mma.sync.aligned.m16n8k16.row.col.f32.f16.f16.f32 "
                "{%0,%1,%2,%3}, {%4,%5,%6,%7}, {%8,%9}, {%0,%1,%2,%3};"
                : "+f"(acc[mt][nt][0]), "+f"(acc[mt][nt][1]),
                  "+f"(acc[mt][nt][2]), "+f"(acc[mt][nt][3])
                : "r"(a[0]), "r"(a[1]), "r"(a[2]), "r"(a[3]),
                  "r"(b[nt][0]), "r"(b[nt][1]));
        }
    };

    const int NKT = KDIM / BK;   // 32
    produce(0);
    produce(1);

#pragma unroll 1
    for (int s = 0; s < NKT; ++s) {
        MBARRIER_WAIT(mb_full + 8 * cslot, cphase);
        const uint32_t sbase = stage0 + cslot * STAGE_BYTES;

        // slabs 0..6: full LDSM/MMA interleave
#pragma unroll
        for (int kk = 0; kk < 7; ++kk) {
            const uint32_t kof = kk * 32;
            uint32_t a[4][4], b[4][2];
            LDSM_X4(b[0][0], b[0][1], b[1][0], b[1][1], sbase + boff[0] + kof);
            LDSM_X4(b[2][0], b[2][1], b[3][0], b[3][1], sbase + boff[1] + kof);
            LDSM_X4(a[0][0], a[0][1], a[0][2], a[0][3], sbase + aoff[0] + kof);
            LDSM_X4(a[1][0], a[1][1], a[1][2], a[1][3], sbase + aoff[1] + kof);
            mma_row(0, a[0], b);
            LDSM_X4(a[2][0], a[2][1], a[2][2], a[2][3], sbase + aoff[2] + kof);
            mma_row(1, a[1], b);
            LDSM_X4(a[3][0], a[3][1], a[3][2], a[3][3], sbase + aoff[3] + kof);
            mma_row(2, a[2], b);
            mma_row(3, a[3], b);
        }
        // slab 7: load all frags, release slot, refill it, then MMA
        {
            const uint32_t kof = 7 * 32;
            uint32_t a[4][4], b[4][2];
            LDSM_X4(b[0][0], b[0][1], b[1][0], b[1][1], sbase + boff[0] + kof);
            LDSM_X4(b[2][0], b[2][1], b[3][0], b[3][1], sbase + boff[1] + kof);
            LDSM_X4(a[0][0], a[0][1], a[0][2], a[0][3], sbase + aoff[0] + kof);
            LDSM_X4(a[1][0], a[1][1], a[1][2], a[1][3], sbase + aoff[1] + kof);
            LDSM_X4(a[2][0], a[2][1], a[2][2], a[2][3], sbase + aoff[2] + kof);
            LDSM_X4(a[3][0], a[3][1], a[3][2], a[3][3], sbase + aoff[3] + kof);
            MBARRIER_ARRIVE(mb_empty + 8 * cslot);   // all stage reads issued
            if (s + 2 < NKT) produce(s + 2);         // refill just-released slot
            mma_row(0, a[0], b);
            mma_row(1, a[1], b);
            mma_row(2, a[2], b);
            mma_row(3, a[3], b);
        }
        if (++cslot == NSTAGE) { cslot = 0; cphase ^= 1; }
    }

    // epilogue: direct fp32 stores
#pragma unroll
    for (int mt = 0; mt < 4; ++mt) {
        const int row0 = bm + wm * 64 + mt * 16 + g;
#pragma unroll
        for (int nt = 0; nt < 4; ++nt) {
            const int col = bn + wn * 32 + nt * 8 + tg * 2;
            *(float2*)&out[(size_t)row0 * NDIM + col] =
                make_float2(acc[mt][nt][0], acc[mt][nt][1]);
            *(float2*)&out[(size_t)(row0 + 8) * NDIM + col] =
                make_float2(acc[mt][nt][2], acc[mt][nt][3]);
        }
    }
}

// ---------------------------------------------------------------------------
extern "C" void kernel_launch(void* const* d_in, const int* in_sizes, int n_in,
                              void* d_out, int out_size) {
    const float* x  = (const float*)d_in[0];
    const int*   wp = (const int*)d_in[1];
    const float* ws = (const float*)d_in[2];
    float* out = (float*)d_out;

    fused_convert_kernel<<<XBLK + WBLK, CVT_THREADS>>>(x, wp, ws);

    static bool attr_set = false;
    if (!attr_set) {
        cudaFuncSetAttribute(gemm_hmma_kernel,
                             cudaFuncAttributeMaxDynamicSharedMemorySize, SMEM_TOTAL);
        attr_set = true;
    }
    dim3 grid(NDIM / BN, TOKENS / BM);
    gemm_hmma_kernel<<<grid, 512, SMEM_TOTAL>>>(out);
}

// round 15
// speedup vs baseline: 1.1286x; 1.1286x over previous
#include <cuda_runtime.h>
#include <cuda_fp16.h>
#include <cstdint>
#include <cstddef>

#define TOKENS 8192
#define KDIM   4096
#define NDIM   4096
#define NGROUPS 32

// fp16 scratch in device globals (allocation-free rule)
__device__ uint4 g_Xh4[(size_t)TOKENS * KDIM / 8];  // x as half
__device__ uint4 g_Wh4[(size_t)NDIM   * KDIM / 8];  // W as half, scale pre-applied

// ---------------------------------------------------------------------------
// Fused converter (proven: ~34 us combined, near HBM roofline)
// ---------------------------------------------------------------------------
#define CVT_THREADS 512
#define XBLK ((int)(TOKENS * (size_t)KDIM / 16 / CVT_THREADS))   // 4096 blocks
#define WBLK ((int)(NDIM   * (size_t)KDIM / 8  / CVT_THREADS))   // 4096 blocks

__global__ void __launch_bounds__(CVT_THREADS)
fused_convert_kernel(const float* __restrict__ x,
                     const int* __restrict__ wp,
                     const float* __restrict__ sc) {
    int b = blockIdx.x;
    if (b < XBLK) {
        size_t idx = ((size_t)b * CVT_THREADS + threadIdx.x) * 2;
        const float4* xv = (const float4*)x;
#pragma unroll
        for (int r = 0; r < 2; ++r) {
            float4 v0 = xv[2 * (idx + r)];
            float4 v1 = xv[2 * (idx + r) + 1];
            __half2 h0 = __floats2half2_rn(v0.x, v0.y);
            __half2 h1 = __floats2half2_rn(v0.z, v0.w);
            __half2 h2 = __floats2half2_rn(v1.x, v1.y);
            __half2 h3 = __floats2half2_rn(v1.z, v1.w);
            uint4 o;
            o.x = *reinterpret_cast<unsigned*>(&h0);
            o.y = *reinterpret_cast<unsigned*>(&h1);
            o.z = *reinterpret_cast<unsigned*>(&h2);
            o.w = *reinterpret_cast<unsigned*>(&h3);
            g_Xh4[idx + r] = o;
        }
    } else {
        size_t idx = (size_t)(b - XBLK) * CVT_THREADS + threadIdx.x;
        int4 p = ((const int4*)wp)[idx];
        int n = (int)(idx >> 9);
        int k = (int)((idx << 3) & (KDIM - 1));
        float s = __ldg(&sc[(size_t)n * NGROUPS + (k >> 7)]);
        __align__(16) __half h[8];
        h[0] = __float2half_rn((float)((p.x & 15) - 8) * s);
        h[1] = __float2half_rn((float)(((p.x >> 4) & 15) - 8) * s);
        h[2] = __float2half_rn((float)((p.y & 15) - 8) * s);
        h[3] = __float2half_rn((float)(((p.y >> 4) & 15) - 8) * s);
        h[4] = __float2half_rn((float)((p.z & 15) - 8) * s);
        h[5] = __float2half_rn((float)(((p.z >> 4) & 15) - 8) * s);
        h[6] = __float2half_rn((float)((p.w & 15) - 8) * s);
        h[7] = __float2half_rn((float)(((p.w >> 4) & 15) - 8) * s);
        g_Wh4[idx] = *reinterpret_cast<uint4*>(h);
    }
}

// ---------------------------------------------------------------------------
// GEMM: CTA 128x256, BK=64, 3-slot mbarrier pipeline (no __syncthreads in
// mainloop), 512 threads (16 warps, 2x8), warp tile 64x32, ldmatrix.
// cp.async (+L2::256B prefetch) completion via mbarrier.arrive.noinc (512).
// Early empty-release after last LDSM; produce() after slab-0 frag loads.
// ---------------------------------------------------------------------------
#define BM 128
#define BN 256
#define BK 64
#define NSTAGE 3
#define SAS 72
#define A_SMEM_BYTES (BM * SAS * 2)
#define B_SMEM_BYTES (BN * SAS * 2)
#define STAGE_BYTES (A_SMEM_BYTES + B_SMEM_BYTES)   // 55296
#define SMEM_TOTAL (1024 + NSTAGE * STAGE_BYTES)    // 166912

#define CP16(dst, src) \
    asm volatile("cp.async.cg.shared.global.L2::256B [%0], [%1], 16;" :: "r"(dst), "l"(src))
#define LDSM_X4(r0, r1, r2, r3, addr) \
    asm volatile("ldmatrix.sync.aligned.m8n8.x4.shared.b16 {%0,%1,%2,%3}, [%4];" \
        : "=r"(r0), "=r"(r1), "=r"(r2), "=r"(r3) : "r"(addr))

#define MBARRIER_INIT(addr, cnt) \
    asm volatile("mbarrier.init.shared.b64 [%0], %1;" :: "r"(addr), "r"(cnt) : "memory")
#define MBARRIER_ARRIVE(addr) \
    asm volatile("mbarrier.arrive.release.cta.shared.b64 _, [%0];" :: "r"(addr) : "memory")
#define CPASYNC_MBAR_ARRIVE_NOINC(addr) \
    asm volatile("cp.async.mbarrier.arrive.noinc.shared.b64 [%0];" :: "r"(addr) : "memory")

#define MBARRIER_WAIT(mbar, par) do { \
    uint32_t _m = (mbar), _p = (par), _d; \
    asm volatile("{\n\t.reg .pred p;\n\tmbarrier.try_wait.parity.shared.b64 p, [%1], %2;\n\tselp.b32 %0, 1, 0, p;\n\t}" \
        : "=r"(_d) : "r"(_m), "r"(_p) : "memory"); \
    if (!_d) { \
        asm volatile("{\n\t.reg .pred P1;\n\tWL_%=:\n\tmbarrier.try_wait.parity.shared.b64 P1, [%0], %1;\n\t@P1 bra.uni WD_%=;\n\tbra.uni WL_%=;\n\tWD_%=:\n\t}" \
            :: "r"(_m), "r"(_p) : "memory"); \
    } \
} while (0)

__device__ __forceinline__ uint32_t smem_u32(const void* p) {
    uint32_t a;
    asm("{ .reg .u64 t; cvta.to.shared.u64 t, %1; cvt.u32.u64 %0, t; }" : "=r"(a) : "l"(p));
    return a;
}

__global__ void __launch_bounds__(512, 1)
gemm_hmma_kernel(float* __restrict__ out) {
    extern __shared__ __align__(128) char smem[];
    const uint32_t sb = smem_u32(smem);
    const uint32_t mb_full  = sb;        // 3 x 8B
    const uint32_t mb_empty = sb + 24;   // 3 x 8B
    const uint32_t stage0   = sb + 1024;

    const int tid  = threadIdx.x;
    const int warp = tid >> 5;
    const int lane = tid & 31;
    const int wm = warp >> 3;      // 0..1 -> 64 rows
    const int wn = warp & 7;       // 0..7 -> 32 cols
    const int g  = lane >> 2;
    const int tg = lane & 3;

    const int bm = blockIdx.y * BM;
    const int bn = blockIdx.x * BN;

    const __half* __restrict__ Xh = (const __half*)g_Xh4;
    const __half* __restrict__ Wh = (const __half*)g_Wh4;

    if (tid == 0) {
#pragma unroll
        for (int s = 0; s < NSTAGE; s++) {
            MBARRIER_INIT(mb_full  + 8 * s, 512);
            MBARRIER_INIT(mb_empty + 8 * s, 512);
        }
    }
    __syncthreads();

    uint32_t aoff[4];
#pragma unroll
    for (int mt = 0; mt < 4; ++mt)
        aoff[mt] = ((wm * 64 + mt * 16 + (lane & 15)) * SAS + ((lane >> 4) << 3)) * 2;
    uint32_t boff[2];
#pragma unroll
    for (int p = 0; p < 2; ++p)
        boff[p] = A_SMEM_BYTES +
                  ((wn * 32 + p * 16 + (lane & 7) + (((lane >> 4) & 1) << 3)) * SAS +
                   (((lane >> 3) & 1) << 3)) * 2;

    float acc[4][4][4];
#pragma unroll
    for (int i = 0; i < 4; i++)
#pragma unroll
        for (int j = 0; j < 4; j++)
#pragma unroll
            for (int r = 0; r < 4; r++) acc[i][j][r] = 0.f;

    int pslot = 0, pphase = 1;   // fresh-barrier parity trick: first wait passes
    int cslot = 0, cphase = 0;

    auto produce = [&](int kt) {
        MBARRIER_WAIT(mb_empty + 8 * pslot, pphase);
        const uint32_t sbase = stage0 + pslot * STAGE_BYTES;
        const int k0 = kt * BK;
#pragma unroll
        for (int i = 0; i < 2; ++i) {
            int c = tid + i * 512;
            int row = c >> 3, col = (c & 7) << 3;
            CP16(sbase + (row * SAS + col) * 2,
                 Xh + (size_t)(bm + row) * KDIM + k0 + col);
        }
#pragma unroll
        for (int i = 0; i < 4; ++i) {
            int c = tid + i * 512;
            int row = c >> 3, col = (c & 7) << 3;
            CP16(sbase + A_SMEM_BYTES + (row * SAS + col) * 2,
                 Wh + (size_t)(bn + row) * KDIM + k0 + col);
        }
        CPASYNC_MBAR_ARRIVE_NOINC(mb_full + 8 * pslot);
        if (++pslot == NSTAGE) { pslot = 0; pphase ^= 1; }
    };

    auto mma_row = [&](int mt, const uint32_t a[4], const uint32_t b[4][2]) {
#pragma unroll
        for (int nt = 0; nt < 4; ++nt) {
            asm volatile(
                "mma.sync.aligned.m16n8k16.row.col.f32.f16.f16.f32 "
                "{%0,%1,%2,%3}, {%4,%5,%6,%7}, {%8,%9}, {%0,%1,%2,%3};"
                : "+f"(acc[mt][nt][0]), "+f"(acc[mt][nt][1]),
                  "+f"(acc[mt][nt][2]), "+f"(acc[mt][nt][3])
                : "r"(a[0]), "r"(a[1]), "r"(a[2]), "r"(a[3]),
                  "r"(b[nt][0]), "r"(b[nt][1]));
        }
    };

    const int NKT = KDIM / BK;   // 64
    produce(0);
    produce(1);

#pragma unroll 1
    for (int s = 0; s < NKT; ++s) {
        MBARRIER_WAIT(mb_full + 8 * cslot, cphase);
        const uint32_t sbase = stage0 + cslot * STAGE_BYTES;
#pragma unroll
        for (int kk = 0; kk < 4; ++kk) {
            const uint32_t kof = kk * 32;
            uint32_t a[4][4], b[4][2];
            // B first, then a[0..1]; weave remaining a-loads between MMA rows
            LDSM_X4(b[0][0], b[0][1], b[1][0], b[1][1], sbase + boff[0] + kof);
            LDSM_X4(b[2][0], b[2][1], b[3][0], b[3][1], sbase + boff[1] + kof);
            LDSM_X4(a[0][0], a[0][1], a[0][2], a[0][3], sbase + aoff[0] + kof);
            LDSM_X4(a[1][0], a[1][1], a[1][2], a[1][3], sbase + aoff[1] + kof);
            // stage s+2 production deferred until the stage's first LDSMs are
            // in flight (keeps the first MMA's critical path short)
            if (kk == 0 && s + 2 < NKT) produce(s + 2);
            mma_row(0, a[0], b);
            LDSM_X4(a[2][0], a[2][1], a[2][2], a[2][3], sbase + aoff[2] + kof);
            mma_row(1, a[1], b);
            LDSM_X4(a[3][0], a[3][1], a[3][2], a[3][3], sbase + aoff[3] + kof);
            // after the stage's last LDSM, release the slot (arrive = release op)
            if (kk == 3) MBARRIER_ARRIVE(mb_empty + 8 * cslot);
            mma_row(2, a[2], b);
            mma_row(3, a[3], b);
        }
        if (++cslot == NSTAGE) { cslot = 0; cphase ^= 1; }
    }

    // epilogue: direct fp32 stores
#pragma unroll
    for (int mt = 0; mt < 4; ++mt) {
        const int row0 = bm + wm * 64 + mt * 16 + g;
#pragma unroll
        for (int nt = 0; nt < 4; ++nt) {
            const int col = bn + wn * 32 + nt * 8 + tg * 2;
            *(float2*)&out[(size_t)row0 * NDIM + col] =
                make_float2(acc[mt][nt][0], acc[mt][nt][1]);
            *(float2*)&out[(size_t)(row0 + 8) * NDIM + col] =
                make_float2(acc[mt][nt][2], acc[mt][nt][3]);
        }
    }
}

// ---------------------------------------------------------------------------
extern "C" void kernel_launch(void* const* d_in, const int* in_sizes, int n_in,
                              void* d_out, int out_size) {
    const float* x  = (const float*)d_in[0];
    const int*   wp = (const int*)d_in[1];
    const float* ws = (const float*)d_in[2];
    float* out = (float*)d_out;

    fused_convert_kernel<<<XBLK + WBLK, CVT_THREADS>>>(x, wp, ws);

    static bool attr_set = false;
    if (!attr_set) {
        cudaFuncSetAttribute(gemm_hmma_kernel,
                             cudaFuncAttributeMaxDynamicSharedMemorySize, SMEM_TOTAL);
        attr_set = true;
    }
    dim3 grid(NDIM / BN, TOKENS / BM);
    gemm_hmma_kernel<<<grid, 512, SMEM_TOTAL>>>(out);
}